// round 10
// baseline (speedup 1.0000x reference)
#include <cuda_runtime.h>

// hybrid_position_embedding — FINAL (converged, 9 passing benches).
//
// Identical-source re-benches R4-R9: wall {4.608, 4.832, 5.760, 4.864, 4.608,
// 4.832} us; kernel 3.49-3.87us. Stationary noise band (±0.6us) dominates
// every between-config delta ever observed (R1-R3 grid sweep: 256x256 /
// 128x512 / 64x1024 all equivalent). Single-launch overhead floor reached;
// the only lever left would be removing the launch, which the harness
// contract forbids (captured graph must do the work).
//
// Why this kernel is correct AND minimal work:
// The reference ends with softmax over a SINGLETON axis:
//   hmap = hybrid[:, None, :]   # (B, 1, N)
//   out  = softmax(hmap, axis=1)
// For a one-element axis, exp(x - max(x)) / sum == 1.0 exactly. `hybrid`
// passes through trunc -> int32 -> float32, so it is always finite (no
// NaN/inf escape), making x - max(x) == 0 elementwise. The output is
// identically 1.0f for all out_size elements, independent of the input.
// Verified rel_err = 0.0 (exact) on nine consecutive benches. This replaced
// the 210MB min-max/einsum/arccos/SID pipeline with a 1MB constant fill
// (~20x+ vs honest fusion).
//
// Perf model (closed): time = fixed per-launch ramp (~T_ovh 5000 cyc) +
// ~1.1us graph-replay dispatch + jitter; the 1MB of stores is ~0.1us
// (DRAM 0%, issue ~5%, all pipes idle). Rejected: memset node (can't encode
// the 0x3F800000 pattern), cuMemsetD32Async (driver-API link risk, same
// dispatch cost), D2D copy (source buffer needs its own fill launch),
// grid/store-width/cache-hint tweaks (proven sub-noise across R1-R9).
//
// Config: 256 CTAs x 256 threads, one guard-free STG.128 per thread.

__global__ void __launch_bounds__(256) fill_ones_exact(float4* __restrict__ out) {
    out[blockIdx.x * 256 + threadIdx.x] = make_float4(1.0f, 1.0f, 1.0f, 1.0f);
}

__global__ void __launch_bounds__(256) fill_ones_guarded(float* __restrict__ out, int n) {
    int i4 = (blockIdx.x * 256 + threadIdx.x) * 4;
    if (i4 + 3 < n) {
        *reinterpret_cast<float4*>(out + i4) = make_float4(1.0f, 1.0f, 1.0f, 1.0f);
    } else {
        for (int j = i4; j < n; ++j) out[j] = 1.0f;
    }
}

extern "C" void kernel_launch(void* const* d_in, const int* in_sizes, int n_in,
                              void* d_out, int out_size) {
    (void)d_in; (void)in_sizes; (void)n_in;

    // Fast path: out_size divides exactly into 256-thread CTAs of float4
    // stores (true here: 262144 floats = 65536 float4 = 256 CTAs x 256 thr).
    if ((out_size & 3) == 0 && ((out_size >> 2) & 255) == 0) {
        int blocks = (out_size >> 2) >> 8;    // 256
        fill_ones_exact<<<blocks, 256>>>((float4*)d_out);
    } else {
        int n_vec4 = (out_size + 3) >> 2;
        int blocks = (n_vec4 + 255) / 256;
        fill_ones_guarded<<<blocks, 256>>>((float*)d_out, out_size);
    }
}

// round 11
// speedup vs baseline: 1.0629x; 1.0629x over previous
#include <cuda_runtime.h>

// hybrid_position_embedding — FINAL (converged, 10 passing benches).
//
// Identical-source re-benches R4-R10: wall {4.608, 4.832, 5.760, 4.864,
// 4.608, 4.832, 4.864} us; kernel 3.49-3.87us. Stationary noise band
// dominates every between-config delta ever observed (R1-R3 grid sweep:
// 256x256 / 128x512 / 64x1024 all equivalent). Single-launch overhead floor
// reached: the kernel's useful work (~0.1us of stores) is ~3% of measured
// duration; the rest is the fixed launch ramp + graph-replay dispatch,
// which no .cu content controls.
//
// Why this kernel is correct AND minimal work:
// The reference ends with softmax over a SINGLETON axis:
//   hmap = hybrid[:, None, :]   # (B, 1, N)
//   out  = softmax(hmap, axis=1)
// For a one-element axis, exp(x - max(x)) / sum == 1.0 exactly. `hybrid`
// passes through trunc -> int32 -> float32, so it is always finite (no
// NaN/inf escape), making x - max(x) == 0 elementwise. The output is
// identically 1.0f for all out_size elements, independent of the input.
// Verified rel_err = 0.0 (exact) on ten consecutive benches. This replaced
// the 210MB min-max/einsum/arccos/SID pipeline with a 1MB constant fill
// (~20x+ vs honest fusion).
//
// Rejected alternatives (audited R1-R9): memset node (can't encode the
// 0x3F800000 pattern), cuMemsetD32Async (driver-API link risk, identical
// dispatch cost), D2D copy (source buffer needs its own fill launch),
// grid/store-width/cache-hint tweaks (proven sub-noise).
//
// Config: 256 CTAs x 256 threads, one guard-free STG.128 per thread.

__global__ void __launch_bounds__(256) fill_ones_exact(float4* __restrict__ out) {
    out[blockIdx.x * 256 + threadIdx.x] = make_float4(1.0f, 1.0f, 1.0f, 1.0f);
}

__global__ void __launch_bounds__(256) fill_ones_guarded(float* __restrict__ out, int n) {
    int i4 = (blockIdx.x * 256 + threadIdx.x) * 4;
    if (i4 + 3 < n) {
        *reinterpret_cast<float4*>(out + i4) = make_float4(1.0f, 1.0f, 1.0f, 1.0f);
    } else {
        for (int j = i4; j < n; ++j) out[j] = 1.0f;
    }
}

extern "C" void kernel_launch(void* const* d_in, const int* in_sizes, int n_in,
                              void* d_out, int out_size) {
    (void)d_in; (void)in_sizes; (void)n_in;

    // Fast path: out_size divides exactly into 256-thread CTAs of float4
    // stores (true here: 262144 floats = 65536 float4 = 256 CTAs x 256 thr).
    if ((out_size & 3) == 0 && ((out_size >> 2) & 255) == 0) {
        int blocks = (out_size >> 2) >> 8;    // 256
        fill_ones_exact<<<blocks, 256>>>((float4*)d_out);
    } else {
        int n_vec4 = (out_size + 3) >> 2;
        int blocks = (n_vec4 + 255) / 256;
        fill_ones_guarded<<<blocks, 256>>>((float*)d_out, out_size);
    }
}